// round 14
// baseline (speedup 1.0000x reference)
#include <cuda_runtime.h>

// Problem constants
#define BATCH   256
#define INDIM   159     // L1*(DIM+1) + L2
#define MDIM    93      // L2*DIM
#define MATEL   2976
#define KPATHS  64
#define NCLS    10
#define SIGDIM  340     // 4+16+64+256
#define KD      159
#define KC      40      // gemm k-chunk

typedef unsigned long long ull;

// ---------------- scratch (no allocations allowed) ----------------
__device__ __align__(16) float g_mean[BATCH * MDIM];
__device__ __align__(16) float g_cov [BATCH * MATEL];
__device__ __align__(16) float g_newV[BATCH * MDIM * KPATHS];   // [b][r][k]
__device__ __align__(16) float g_logits[BATCH * NCLS];          // atomic accumulators
__device__ unsigned int g_ticket;                               // last-block election

// ---------------- f32x2 packed helpers (sm_103a FFMA2 path) ----------------
__device__ __forceinline__ ull pk2(float lo, float hi) {
    ull r; asm("mov.b64 %0, {%1,%2};" : "=l"(r) : "f"(lo), "f"(hi)); return r;
}
__device__ __forceinline__ void upk2(ull v, float& lo, float& hi) {
    asm("mov.b64 {%0,%1}, %2;" : "=f"(lo), "=f"(hi) : "l"(v));
}
__device__ __forceinline__ ull fma2_(ull a, ull b, ull c) {
    ull d; asm("fma.rn.f32x2 %0, %1, %2, %3;" : "=l"(d) : "l"(a), "l"(b), "l"(c)); return d;
}
__device__ __forceinline__ ull mul2_(ull a, ull b) {
    ull d; asm("mul.rn.f32x2 %0, %1, %2;" : "=l"(d) : "l"(a), "l"(b)); return d;
}
__device__ __forceinline__ ull add2_(ull a, ull b) {
    ull d; asm("add.rn.f32x2 %0, %1, %2;" : "=l"(d) : "l"(a), "l"(b)); return d;
}

// =====================================================================
// Kernel 1 (fused): mean = x@W_mean^T + b_mean AND cov = x@W_cov^T + b_cov
// SCALAR 4x4 thread tiles, 32 batch x 128 n block tile -> grid 25x8 =
// 200 blocks (full 148-SM coverage) and 2 blocks/SM (25% occ).
// is_mean blocks also zero g_logits + g_ticket (stream-ordered pre-sig).
// =====================================================================
__global__ __launch_bounds__(256, 2) void gemm_kernel(
    const float* __restrict__ X,
    const float* __restrict__ Wc, const float* __restrict__ bc,
    const float* __restrict__ Wm, const float* __restrict__ bm)
{
    __shared__ float Ash[32][KC + 1];   // 5.25 KB, row-major (conflict-free)
    __shared__ float Wsh[KC][132];      // 20.6 KB

    bool is_mean = (blockIdx.x == 24);
    const float* W    = is_mean ? Wm : Wc;
    const float* bias = is_mean ? bm : bc;
    float*       out  = is_mean ? g_mean : g_cov;
    int N  = is_mean ? MDIM : MATEL;
    int n0 = is_mean ? 0 : blockIdx.x * 128;
    int b0 = blockIdx.y * 32;
    int tid = threadIdx.x;

    if (is_mean) {
        for (int i = tid; i < BATCH * NCLS; i += 256) g_logits[i] = 0.f;
        if (tid == 0) g_ticket = 0u;
    }

    float acc[4][4] = {};
    int tn = tid & 31;                  // 4 consecutive n
    int tb = tid >> 5;                  // 4 consecutive batch rows

    for (int k0 = 0; k0 < KD; k0 += KC) {
        __syncthreads();
        for (int idx = tid; idx < 32 * KC; idx += 256) {
            int r = idx / KC, k = idx % KC;
            int gk = k0 + k;
            Ash[r][k] = (gk < KD) ? X[(b0 + r) * KD + gk] : 0.f;
        }
        for (int idx = tid; idx < KC * 128; idx += 256) {
            int n = idx / KC, k = idx % KC;
            int gk = k0 + k, gn = n0 + n;
            Wsh[k][n] = (gk < KD && gn < N) ? W[(size_t)gn * KD + gk] : 0.f;
        }
        __syncthreads();
        #pragma unroll 8
        for (int k = 0; k < KC; k++) {
            float4 w = *(const float4*)&Wsh[k][tn * 4];
            #pragma unroll
            for (int j = 0; j < 4; j++) {
                float a = Ash[tb * 4 + j][k];
                acc[j][0] = fmaf(a, w.x, acc[j][0]);
                acc[j][1] = fmaf(a, w.y, acc[j][1]);
                acc[j][2] = fmaf(a, w.z, acc[j][2]);
                acc[j][3] = fmaf(a, w.w, acc[j][3]);
            }
        }
    }
    #pragma unroll
    for (int j = 0; j < 4; j++)
        #pragma unroll
        for (int i = 0; i < 4; i++) {
            int n = n0 + tn * 4 + i;
            if (n < N)
                out[(size_t)(b0 + tb * 4 + j) * N + n] = acc[j][i] + bias[n];
        }
}

// =====================================================================
// Kernel 2: scatter sqrtCov -> banded M (93x93), newV = M@eps + mean.
// 3-row register blocking; balanced band pairing (tg with 30-tg).
// =====================================================================
__global__ __launch_bounds__(256) void newv_kernel(
    const float* __restrict__ eps, const int* __restrict__ xI,
    const int* __restrict__ yI)
{
    __shared__ float Msh[MDIM * MDIM];
    int b   = blockIdx.x;
    int tid = threadIdx.x;

    for (int i = tid; i < MDIM * MDIM; i += 256) Msh[i] = 0.f;
    __syncthreads();
    const float* covB = g_cov + (size_t)b * MATEL;
    for (int e = tid; e < MATEL; e += 256)
        Msh[xI[e] * MDIM + yI[e]] = covB[e];
    __syncthreads();

    int k4 = tid & 15;
    int tg = tid >> 4;
    const float* epsB = eps    + (size_t)b * MDIM * KPATHS + k4 * 4;
    float*       outB = g_newV + (size_t)b * MDIM * KPATHS + k4 * 4;

    #pragma unroll
    for (int pass = 0; pass < 2; pass++) {
        if (pass == 1 && tg == 15) break;
        int g    = pass ? 30 - tg : tg;
        int r0   = 3 * g;
        int cmax = 3 * g + 3;
        float a0x=0,a0y=0,a0z=0,a0w=0, a1x=0,a1y=0,a1z=0,a1w=0, a2x=0,a2y=0,a2z=0,a2w=0;
        const float* M0 = &Msh[r0 * MDIM];
        for (int c = 0; c < cmax; c++) {
            float4 ev = *(const float4*)(epsB + (size_t)c * KPATHS);
            float m0 = M0[c], m1 = M0[MDIM + c], m2 = M0[2 * MDIM + c];
            a0x = fmaf(m0, ev.x, a0x); a0y = fmaf(m0, ev.y, a0y);
            a0z = fmaf(m0, ev.z, a0z); a0w = fmaf(m0, ev.w, a0w);
            a1x = fmaf(m1, ev.x, a1x); a1y = fmaf(m1, ev.y, a1y);
            a1z = fmaf(m1, ev.z, a1z); a1w = fmaf(m1, ev.w, a1w);
            a2x = fmaf(m2, ev.x, a2x); a2y = fmaf(m2, ev.y, a2y);
            a2z = fmaf(m2, ev.z, a2z); a2w = fmaf(m2, ev.w, a2w);
        }
        float mn0 = g_mean[b * MDIM + r0];
        float mn1 = g_mean[b * MDIM + r0 + 1];
        float mn2 = g_mean[b * MDIM + r0 + 2];
        *(float4*)(outB + (size_t)(r0    ) * KPATHS) = make_float4(a0x+mn0, a0y+mn0, a0z+mn0, a0w+mn0);
        *(float4*)(outB + (size_t)(r0 + 1) * KPATHS) = make_float4(a1x+mn1, a1y+mn1, a1z+mn1, a1w+mn1);
        *(float4*)(outB + (size_t)(r0 + 2) * KPATHS) = make_float4(a2x+mn2, a2y+mn2, a2z+mn2, a2w+mn2);
    }
}

// =====================================================================
// Kernel 3: signature via f32x2 packed Chen steps, TWO PATHS PER LANE,
// precomputed packed deltas in shared. 256 thr = 32 paths; grid = B*2;
// 3 blocks/SM. Epilogue: norms, Newton lambda, expected-sig, logit
// contraction -> global atomics; LAST block (ticket) runs log_softmax
// for all 256 rows and writes the output (no separate final kernel).
// =====================================================================
__device__ __forceinline__ void solve_lam(float n1, float n2, float n3, float n4,
                                          float& lam, float& lam2v,
                                          float& lam3, float& lam4)
{
    float norm2 = 1.0f + (((n1 + n2) + n3) + n4);
    float xc  = fmaxf(norm2, 4.0f);
    float psi = (norm2 <= 4.0f) ? norm2 : (4.0f + 16.0f * (0.25f - 1.0f / xc));
    float q = psi - 1.0f;
    float t = 1.0f;
    t = fminf(t, q / n1);
    t = fminf(t, sqrtf(q / n2));
    t = fminf(t, exp2f((1.0f / 3.0f) * log2f(q / n3)));
    t = fminf(t, sqrtf(sqrtf(q / n4)));
    float cN = -q;
    #pragma unroll
    for (int it = 0; it < 12; it++) {
        float f  = fmaf(fmaf(fmaf(fmaf(n4, t, n3), t, n2), t, n1), t, cN);
        float fp = fmaf(fmaf(fmaf(4.0f * n4, t, 3.0f * n3), t, 2.0f * n2), t, n1);
        fp = fmaxf(fp, 1e-30f);
        t  = fmaxf(t - f / fp, 0.0f);
    }
    lam2v = t;
    lam   = sqrtf(t);
    lam3  = lam2v * lam;
    lam4  = lam2v * lam2v;
}

__global__ __launch_bounds__(256, 3) void sig_kernel(
    const float* __restrict__ x,  const float* __restrict__ Wf,
    const float* __restrict__ bf, float* __restrict__ out)
{
    __shared__ float  xsh[INDIM + 1];
    __shared__ float  nvsh[MDIM * 32];          // newV half: [r][k] 11.9 KB
    __shared__ float4 dxsh[62 * 16 * 2];        // packed deltas 31.7 KB
    __shared__ float  sacc[SIGDIM];
    __shared__ unsigned int s_last;

    int b    = blockIdx.x >> 1;
    int kh   = blockIdx.x & 1;                  // k half
    int tid  = threadIdx.x;
    const float* xb = x + (size_t)b * INDIM;

    for (int i = tid; i < INDIM; i += 256) xsh[i] = xb[i];
    const float* nvb = g_newV + (size_t)b * MDIM * KPATHS + kh * 32;
    for (int i = tid; i < MDIM * 32; i += 256)
        nvsh[i] = nvb[(size_t)(i >> 5) * KPATHS + (i & 31)];
    for (int i = tid; i < SIGDIM; i += 256) sacc[i] = 0.f;
    __syncthreads();

    // ---- precompute packed deltas: step s, path-pair pp ----
    for (int i = tid; i < 62 * 16; i += 256) {
        int s = i >> 4, pp = i & 15;
        int m = s >> 1;
        int r = 3 * m;
        int kA = 2 * pp, kB = kA + 1;
        float n0A = nvsh[r * 32 + kA],       n0B = nvsh[r * 32 + kB];
        float n1A = nvsh[(r + 1) * 32 + kA], n1B = nvsh[(r + 1) * 32 + kB];
        float n2A = nvsh[(r + 2) * 32 + kA], n2B = nvsh[(r + 2) * 32 + kB];
        float d0A, d0B, d1A, d1B, d2A, d2B, dt;
        if ((s & 1) == 0) {     // new_m - known_m
            d0A = n0A - xsh[r];     d0B = n0B - xsh[r];
            d1A = n1A - xsh[r + 1]; d1B = n1B - xsh[r + 1];
            d2A = n2A - xsh[r + 2]; d2B = n2B - xsh[r + 2];
            dt  = xsh[128 + m] - xsh[96 + m];
        } else {                // known_{m+1} - new_m
            d0A = xsh[r + 3] - n0A; d0B = xsh[r + 3] - n0B;
            d1A = xsh[r + 4] - n1A; d1B = xsh[r + 4] - n1B;
            d2A = xsh[r + 5] - n2A; d2B = xsh[r + 5] - n2B;
            dt  = xsh[97 + m] - xsh[128 + m];
        }
        float4* d = &dxsh[(s * 16 + pp) * 2];
        d[0] = make_float4(d0A, d0B, d1A, d1B);
        d[1] = make_float4(d2A, d2B, dt, dt);
    }
    __syncthreads();

    // ---- packed signature main loop: 2 paths per lane ----
    int pp  = tid >> 4;
    int pre = tid & 15;
    int i1 = pre >> 2, i2 = pre & 3;
    const char* dbase  = (const char*)&dxsh[pp * 2];
    const char* dubase = dbase + i1 * 8;
    const char* dvbase = dbase + i2 * 8;

    const ull QUARTER = 0x3E8000003E800000ULL;   // (0.25, 0.25)
    const ull HALF    = 0x3F0000003F000000ULL;   // (0.5, 0.5)
    const ull THIRD   = pk2(1.0f / 3.0f, 1.0f / 3.0f);

    ull s1u = 0, s2 = 0;
    ull s3[4] = {0, 0, 0, 0};
    ull s4[16] = {0,0,0,0,0,0,0,0,0,0,0,0,0,0,0,0};

    #pragma unroll 2
    for (int s = 0; s < 62; s++) {
        float4 f0 = ((const float4*)(dbase + s * 512))[0];
        float4 f1 = ((const float4*)(dbase + s * 512))[1];
        ull DX0 = ((ull*)&f0)[0], DX1 = ((ull*)&f0)[1];
        ull DX2 = ((ull*)&f1)[0], DX3 = ((ull*)&f1)[1];
        ull du = *(const ull*)(dubase + s * 512);
        ull dv = *(const ull*)(dvbase + s * 512);

        ull cc1 = fma2_(QUARTER, du, s1u);
        ull cc2 = fma2_(mul2_(THIRD, dv), cc1, s2);
        ull h2  = mul2_(HALF, cc2);
        ull hh;
        hh = fma2_(DX0, h2, s3[0]);
        s4[0]  = fma2_(DX0, hh, s4[0]);  s4[1]  = fma2_(DX1, hh, s4[1]);
        s4[2]  = fma2_(DX2, hh, s4[2]);  s4[3]  = fma2_(DX3, hh, s4[3]);
        hh = fma2_(DX1, h2, s3[1]);
        s4[4]  = fma2_(DX0, hh, s4[4]);  s4[5]  = fma2_(DX1, hh, s4[5]);
        s4[6]  = fma2_(DX2, hh, s4[6]);  s4[7]  = fma2_(DX3, hh, s4[7]);
        hh = fma2_(DX2, h2, s3[2]);
        s4[8]  = fma2_(DX0, hh, s4[8]);  s4[9]  = fma2_(DX1, hh, s4[9]);
        s4[10] = fma2_(DX2, hh, s4[10]); s4[11] = fma2_(DX3, hh, s4[11]);
        hh = fma2_(DX3, h2, s3[3]);
        s4[12] = fma2_(DX0, hh, s4[12]); s4[13] = fma2_(DX1, hh, s4[13]);
        s4[14] = fma2_(DX2, hh, s4[14]); s4[15] = fma2_(DX3, hh, s4[15]);

        ull c1b = fma2_(THIRD, du, s1u);
        ull m3v = fma2_(mul2_(HALF, dv), c1b, s2);
        s3[0] = fma2_(DX0, m3v, s3[0]); s3[1] = fma2_(DX1, m3v, s3[1]);
        s3[2] = fma2_(DX2, m3v, s3[2]); s3[3] = fma2_(DX3, m3v, s3[3]);
        s2 = fma2_(dv, fma2_(HALF, du, s1u), s2);
        s1u = add2_(s1u, du);
    }

    // ---- S1 telescopes (same for all paths/lanes) ----
    float s1c0 = xsh[93] - xsh[0];
    float s1c1 = xsh[94] - xsh[1];
    float s1c2 = xsh[95] - xsh[2];
    float s1c3 = xsh[127] - xsh[96];
    float n1 = s1c0*s1c0 + s1c1*s1c1 + s1c2*s1c2 + s1c3*s1c3;

    ull n2p = mul2_(s2, s2);
    ull n3p = mul2_(s3[0], s3[0]);
    #pragma unroll
    for (int j = 1; j < 4; j++) n3p = fma2_(s3[j], s3[j], n3p);
    ull n4p = mul2_(s4[0], s4[0]);
    #pragma unroll
    for (int j = 1; j < 16; j++) n4p = fma2_(s4[j], s4[j], n4p);
    #pragma unroll
    for (int off = 8; off >= 1; off >>= 1) {
        n2p = add2_(n2p, __shfl_xor_sync(0xffffffffu, n2p, off));
        n3p = add2_(n3p, __shfl_xor_sync(0xffffffffu, n3p, off));
        n4p = add2_(n4p, __shfl_xor_sync(0xffffffffu, n4p, off));
    }
    float n2a, n2b, n3a, n3b, n4a, n4b;
    upk2(n2p, n2a, n2b); upk2(n3p, n3a, n3b); upk2(n4p, n4a, n4b);

    float lamA, l2A, l3A, l4A, lamB, l2B, l3B, l4B;
    solve_lam(n1, n2a, n3a, n4a, lamA, l2A, l3A, l4A);
    solve_lam(n1, n2b, n3b, n4b, lamB, l2B, l3B, l4B);

    // ---- accumulate normalized expected signature ----
    if (pre == 0) {
        float ls = lamA + lamB;
        atomicAdd(&sacc[0], ls * s1c0);
        atomicAdd(&sacc[1], ls * s1c1);
        atomicAdd(&sacc[2], ls * s1c2);
        atomicAdd(&sacc[3], ls * s1c3);
    }
    {
        float a, bb; upk2(s2, a, bb);
        atomicAdd(&sacc[4 + pre], l2A * a + l2B * bb);
    }
    #pragma unroll
    for (int j = 0; j < 4; j++) {
        float a, bb; upk2(s3[j], a, bb);
        atomicAdd(&sacc[20 + pre * 4 + j], l3A * a + l3B * bb);
    }
    #pragma unroll
    for (int j = 0; j < 16; j++) {
        float a, bb; upk2(s4[j], a, bb);
        atomicAdd(&sacc[84 + pre * 16 + j], l4A * a + l4B * bb);
    }
    __syncthreads();

    // ---- logit contraction: class c dot over SIGDIM, 8 warps ----
    int warp = tid >> 5, lane = tid & 31;
    for (int c = warp; c < NCLS; c += 8) {
        float sum = 0.f;
        #pragma unroll
        for (int i = 0; i < 11; i++) {
            int j = lane + i * 32;
            if (j < SIGDIM)
                sum = fmaf(sacc[j], __ldg(&Wf[c * SIGDIM + j]), sum);
        }
        #pragma unroll
        for (int off = 16; off; off >>= 1)
            sum += __shfl_xor_sync(0xffffffffu, sum, off);
        if (lane == 0) {
            atomicAdd(&g_logits[b * NCLS + c], sum);
            __threadfence();        // order this thread's logit add before ticket
        }
    }
    __syncthreads();

    // ---- last-block election: loser blocks exit, winner does softmax ----
    if (tid == 0) {
        __threadfence();
        s_last = (atomicAdd(&g_ticket, 1u) == 2u * BATCH - 1u) ? 1u : 0u;
    }
    __syncthreads();
    if (s_last) {
        for (int rb = warp; rb < BATCH; rb += 8) {
            float logit = -3.402823466e38f;
            if (lane < NCLS)
                logit = __ldcg(&g_logits[rb * NCLS + lane]) * (1.0f / (float)KPATHS)
                        + bf[lane];
            float mx = logit;
            #pragma unroll
            for (int off = 16; off; off >>= 1)
                mx = fmaxf(mx, __shfl_xor_sync(0xffffffffu, mx, off));
            float e = (lane < NCLS) ? expf(logit - mx) : 0.f;
            float ssum = e;
            #pragma unroll
            for (int off = 16; off; off >>= 1)
                ssum += __shfl_xor_sync(0xffffffffu, ssum, off);
            if (lane < NCLS)
                out[rb * NCLS + lane] = logit - mx - logf(ssum);
        }
    }
}

// =====================================================================
extern "C" void kernel_launch(void* const* d_in, const int* in_sizes, int n_in,
                              void* d_out, int out_size)
{
    const float* x      = (const float*)d_in[0];
    const float* W_mean = (const float*)d_in[1];
    const float* b_mean = (const float*)d_in[2];
    const float* W_cov  = (const float*)d_in[3];
    const float* b_cov  = (const float*)d_in[4];
    const float* W_fin  = (const float*)d_in[5];
    const float* b_fin  = (const float*)d_in[6];
    const float* eps    = (const float*)d_in[7];
    const int*   x_idx  = (const int*)  d_in[8];
    const int*   y_idx  = (const int*)  d_in[9];
    float* out = (float*)d_out;

    // 1) fused linears, 200-block coverage (also zeroes g_logits + g_ticket)
    gemm_kernel<<<dim3(25, BATCH / 32), 256>>>(x, W_cov, b_cov, W_mean, b_mean);
    // 2) banded batched matmul -> newV
    newv_kernel<<<BATCH, 256>>>(eps, x_idx, y_idx);
    // 3) packed-delta f32x2 signatures + logits + last-block softmax/output
    sig_kernel<<<BATCH * 2, 256>>>(x, W_fin, b_fin, out);
}

// round 15
// speedup vs baseline: 1.2190x; 1.2190x over previous
#include <cuda_runtime.h>

// Problem constants
#define BATCH   256
#define INDIM   159     // L1*(DIM+1) + L2
#define MDIM    93      // L2*DIM
#define MATEL   2976
#define KPATHS  64
#define NCLS    10
#define SIGDIM  340     // 4+16+64+256
#define KD      159
#define KC      40      // gemm k-chunk

typedef unsigned long long ull;

// ---------------- scratch (no allocations allowed) ----------------
__device__ __align__(16) float g_mean[BATCH * MDIM];
__device__ __align__(16) float g_cov [BATCH * MATEL];
__device__ __align__(16) float g_newV[BATCH * MDIM * KPATHS];   // [b][r][k]
__device__ __align__(16) float g_logits[BATCH * NCLS];          // atomic accumulators

// ---------------- f32x2 packed helpers (sm_103a FFMA2 path) ----------------
__device__ __forceinline__ ull pk2(float lo, float hi) {
    ull r; asm("mov.b64 %0, {%1,%2};" : "=l"(r) : "f"(lo), "f"(hi)); return r;
}
__device__ __forceinline__ void upk2(ull v, float& lo, float& hi) {
    asm("mov.b64 {%0,%1}, %2;" : "=f"(lo), "=f"(hi) : "l"(v));
}
__device__ __forceinline__ ull fma2_(ull a, ull b, ull c) {
    ull d; asm("fma.rn.f32x2 %0, %1, %2, %3;" : "=l"(d) : "l"(a), "l"(b), "l"(c)); return d;
}
__device__ __forceinline__ ull mul2_(ull a, ull b) {
    ull d; asm("mul.rn.f32x2 %0, %1, %2;" : "=l"(d) : "l"(a), "l"(b)); return d;
}
__device__ __forceinline__ ull add2_(ull a, ull b) {
    ull d; asm("add.rn.f32x2 %0, %1, %2;" : "=l"(d) : "l"(a), "l"(b)); return d;
}

// =====================================================================
// Kernel 1 (fused): mean = x@W_mean^T + b_mean AND cov = x@W_cov^T + b_cov
// CHAMPION CONFIG: 64 batch x 128 n block tile; 8x4 register tile.
// blockIdx.x 0..23 -> cov col-blocks; 24 -> mean (N=93).
// is_mean blocks also zero g_logits (stream-ordered before sig).
// =====================================================================
__global__ __launch_bounds__(256) void gemm_kernel(
    const float* __restrict__ X,
    const float* __restrict__ Wc, const float* __restrict__ bc,
    const float* __restrict__ Wm, const float* __restrict__ bm)
{
    __shared__ float Ash[64][KC + 1];   // 10.5 KB
    __shared__ float Wsh[KC][132];      // 20.6 KB

    bool is_mean = (blockIdx.x == 24);
    const float* W    = is_mean ? Wm : Wc;
    const float* bias = is_mean ? bm : bc;
    float*       out  = is_mean ? g_mean : g_cov;
    int N  = is_mean ? MDIM : MATEL;
    int n0 = is_mean ? 0 : blockIdx.x * 128;
    int b0 = blockIdx.y * 64;
    int tid = threadIdx.x;

    if (is_mean)
        for (int i = tid; i < BATCH * NCLS; i += 256) g_logits[i] = 0.f;

    float acc[8][4] = {};
    int tn = tid & 31;                  // 4 consecutive n
    int tb = tid >> 5;                  // 8 consecutive batch rows

    for (int k0 = 0; k0 < KD; k0 += KC) {
        __syncthreads();
        for (int idx = tid; idx < 64 * KC; idx += 256) {
            int r = idx / KC, k = idx % KC;
            int gk = k0 + k;
            Ash[r][k] = (gk < KD) ? X[(b0 + r) * KD + gk] : 0.f;
        }
        for (int idx = tid; idx < KC * 128; idx += 256) {
            int n = idx / KC, k = idx % KC;
            int gk = k0 + k, gn = n0 + n;
            Wsh[k][n] = (gk < KD && gn < N) ? W[(size_t)gn * KD + gk] : 0.f;
        }
        __syncthreads();
        #pragma unroll 8
        for (int k = 0; k < KC; k++) {
            float4 w = *(const float4*)&Wsh[k][tn * 4];
            #pragma unroll
            for (int j = 0; j < 8; j++) {
                float a = Ash[tb * 8 + j][k];
                acc[j][0] = fmaf(a, w.x, acc[j][0]);
                acc[j][1] = fmaf(a, w.y, acc[j][1]);
                acc[j][2] = fmaf(a, w.z, acc[j][2]);
                acc[j][3] = fmaf(a, w.w, acc[j][3]);
            }
        }
    }
    #pragma unroll
    for (int j = 0; j < 8; j++)
        #pragma unroll
        for (int i = 0; i < 4; i++) {
            int n = n0 + tn * 4 + i;
            if (n < N)
                out[(size_t)(b0 + tb * 8 + j) * N + n] = acc[j][i] + bias[n];
        }
}

// =====================================================================
// Kernel 2: scatter sqrtCov -> banded M (93x93), newV = M@eps + mean.
// 3-row register blocking; balanced band pairing (tg with 30-tg).
// =====================================================================
__global__ __launch_bounds__(256) void newv_kernel(
    const float* __restrict__ eps, const int* __restrict__ xI,
    const int* __restrict__ yI)
{
    __shared__ float Msh[MDIM * MDIM];
    int b   = blockIdx.x;
    int tid = threadIdx.x;

    for (int i = tid; i < MDIM * MDIM; i += 256) Msh[i] = 0.f;
    __syncthreads();
    const float* covB = g_cov + (size_t)b * MATEL;
    for (int e = tid; e < MATEL; e += 256)
        Msh[xI[e] * MDIM + yI[e]] = covB[e];
    __syncthreads();

    int k4 = tid & 15;
    int tg = tid >> 4;
    const float* epsB = eps    + (size_t)b * MDIM * KPATHS + k4 * 4;
    float*       outB = g_newV + (size_t)b * MDIM * KPATHS + k4 * 4;

    #pragma unroll
    for (int pass = 0; pass < 2; pass++) {
        if (pass == 1 && tg == 15) break;
        int g    = pass ? 30 - tg : tg;
        int r0   = 3 * g;
        int cmax = 3 * g + 3;
        float a0x=0,a0y=0,a0z=0,a0w=0, a1x=0,a1y=0,a1z=0,a1w=0, a2x=0,a2y=0,a2z=0,a2w=0;
        const float* M0 = &Msh[r0 * MDIM];
        for (int c = 0; c < cmax; c++) {
            float4 ev = *(const float4*)(epsB + (size_t)c * KPATHS);
            float m0 = M0[c], m1 = M0[MDIM + c], m2 = M0[2 * MDIM + c];
            a0x = fmaf(m0, ev.x, a0x); a0y = fmaf(m0, ev.y, a0y);
            a0z = fmaf(m0, ev.z, a0z); a0w = fmaf(m0, ev.w, a0w);
            a1x = fmaf(m1, ev.x, a1x); a1y = fmaf(m1, ev.y, a1y);
            a1z = fmaf(m1, ev.z, a1z); a1w = fmaf(m1, ev.w, a1w);
            a2x = fmaf(m2, ev.x, a2x); a2y = fmaf(m2, ev.y, a2y);
            a2z = fmaf(m2, ev.z, a2z); a2w = fmaf(m2, ev.w, a2w);
        }
        float mn0 = g_mean[b * MDIM + r0];
        float mn1 = g_mean[b * MDIM + r0 + 1];
        float mn2 = g_mean[b * MDIM + r0 + 2];
        *(float4*)(outB + (size_t)(r0    ) * KPATHS) = make_float4(a0x+mn0, a0y+mn0, a0z+mn0, a0w+mn0);
        *(float4*)(outB + (size_t)(r0 + 1) * KPATHS) = make_float4(a1x+mn1, a1y+mn1, a1z+mn1, a1w+mn1);
        *(float4*)(outB + (size_t)(r0 + 2) * KPATHS) = make_float4(a2x+mn2, a2y+mn2, a2z+mn2, a2w+mn2);
    }
}

// =====================================================================
// Kernel 3: signature via f32x2 packed Chen steps, TWO PATHS PER LANE,
// precomputed packed deltas in shared. 256 thr = 32 paths; grid = B*2;
// 3 blocks/SM. Epilogue: norms, Newton lambda, expected-sig (shared
// atomics), logit contraction -> global atomics.
// =====================================================================
__device__ __forceinline__ void solve_lam(float n1, float n2, float n3, float n4,
                                          float& lam, float& lam2v,
                                          float& lam3, float& lam4)
{
    float norm2 = 1.0f + (((n1 + n2) + n3) + n4);
    float xc  = fmaxf(norm2, 4.0f);
    float psi = (norm2 <= 4.0f) ? norm2 : (4.0f + 16.0f * (0.25f - 1.0f / xc));
    float q = psi - 1.0f;
    float t = 1.0f;
    t = fminf(t, q / n1);
    t = fminf(t, sqrtf(q / n2));
    t = fminf(t, exp2f((1.0f / 3.0f) * log2f(q / n3)));
    t = fminf(t, sqrtf(sqrtf(q / n4)));
    float cN = -q;
    #pragma unroll
    for (int it = 0; it < 12; it++) {
        float f  = fmaf(fmaf(fmaf(fmaf(n4, t, n3), t, n2), t, n1), t, cN);
        float fp = fmaf(fmaf(fmaf(4.0f * n4, t, 3.0f * n3), t, 2.0f * n2), t, n1);
        fp = fmaxf(fp, 1e-30f);
        t  = fmaxf(t - f / fp, 0.0f);
    }
    lam2v = t;
    lam   = sqrtf(t);
    lam3  = lam2v * lam;
    lam4  = lam2v * lam2v;
}

__global__ __launch_bounds__(256, 3) void sig_kernel(
    const float* __restrict__ x,  const float* __restrict__ Wf)
{
    __shared__ float  xsh[INDIM + 1];
    __shared__ float  nvsh[MDIM * 32];          // newV half: [r][k] 11.9 KB
    __shared__ float4 dxsh[62 * 16 * 2];        // packed deltas 31.7 KB
    __shared__ float  sacc[SIGDIM];

    int b    = blockIdx.x >> 1;
    int kh   = blockIdx.x & 1;                  // k half
    int tid  = threadIdx.x;
    const float* xb = x + (size_t)b * INDIM;

    for (int i = tid; i < INDIM; i += 256) xsh[i] = xb[i];
    const float* nvb = g_newV + (size_t)b * MDIM * KPATHS + kh * 32;
    for (int i = tid; i < MDIM * 32; i += 256)
        nvsh[i] = nvb[(size_t)(i >> 5) * KPATHS + (i & 31)];
    for (int i = tid; i < SIGDIM; i += 256) sacc[i] = 0.f;
    __syncthreads();

    // ---- precompute packed deltas: step s, path-pair pp ----
    for (int i = tid; i < 62 * 16; i += 256) {
        int s = i >> 4, pp = i & 15;
        int m = s >> 1;
        int r = 3 * m;
        int kA = 2 * pp, kB = kA + 1;
        float n0A = nvsh[r * 32 + kA],       n0B = nvsh[r * 32 + kB];
        float n1A = nvsh[(r + 1) * 32 + kA], n1B = nvsh[(r + 1) * 32 + kB];
        float n2A = nvsh[(r + 2) * 32 + kA], n2B = nvsh[(r + 2) * 32 + kB];
        float d0A, d0B, d1A, d1B, d2A, d2B, dt;
        if ((s & 1) == 0) {     // new_m - known_m
            d0A = n0A - xsh[r];     d0B = n0B - xsh[r];
            d1A = n1A - xsh[r + 1]; d1B = n1B - xsh[r + 1];
            d2A = n2A - xsh[r + 2]; d2B = n2B - xsh[r + 2];
            dt  = xsh[128 + m] - xsh[96 + m];
        } else {                // known_{m+1} - new_m
            d0A = xsh[r + 3] - n0A; d0B = xsh[r + 3] - n0B;
            d1A = xsh[r + 4] - n1A; d1B = xsh[r + 4] - n1B;
            d2A = xsh[r + 5] - n2A; d2B = xsh[r + 5] - n2B;
            dt  = xsh[97 + m] - xsh[128 + m];
        }
        float4* d = &dxsh[(s * 16 + pp) * 2];
        d[0] = make_float4(d0A, d0B, d1A, d1B);
        d[1] = make_float4(d2A, d2B, dt, dt);
    }
    __syncthreads();

    // ---- packed signature main loop: 2 paths per lane ----
    int pp  = tid >> 4;
    int pre = tid & 15;
    int i1 = pre >> 2, i2 = pre & 3;
    const char* dbase  = (const char*)&dxsh[pp * 2];
    const char* dubase = dbase + i1 * 8;
    const char* dvbase = dbase + i2 * 8;

    const ull QUARTER = 0x3E8000003E800000ULL;   // (0.25, 0.25)
    const ull HALF    = 0x3F0000003F000000ULL;   // (0.5, 0.5)
    const ull THIRD   = pk2(1.0f / 3.0f, 1.0f / 3.0f);

    ull s1u = 0, s2 = 0;
    ull s3[4] = {0, 0, 0, 0};
    ull s4[16] = {0,0,0,0,0,0,0,0,0,0,0,0,0,0,0,0};

    #pragma unroll 2
    for (int s = 0; s < 62; s++) {
        float4 f0 = ((const float4*)(dbase + s * 512))[0];
        float4 f1 = ((const float4*)(dbase + s * 512))[1];
        ull DX0 = ((ull*)&f0)[0], DX1 = ((ull*)&f0)[1];
        ull DX2 = ((ull*)&f1)[0], DX3 = ((ull*)&f1)[1];
        ull du = *(const ull*)(dubase + s * 512);
        ull dv = *(const ull*)(dvbase + s * 512);

        ull cc1 = fma2_(QUARTER, du, s1u);
        ull cc2 = fma2_(mul2_(THIRD, dv), cc1, s2);
        ull h2  = mul2_(HALF, cc2);
        ull hh;
        hh = fma2_(DX0, h2, s3[0]);
        s4[0]  = fma2_(DX0, hh, s4[0]);  s4[1]  = fma2_(DX1, hh, s4[1]);
        s4[2]  = fma2_(DX2, hh, s4[2]);  s4[3]  = fma2_(DX3, hh, s4[3]);
        hh = fma2_(DX1, h2, s3[1]);
        s4[4]  = fma2_(DX0, hh, s4[4]);  s4[5]  = fma2_(DX1, hh, s4[5]);
        s4[6]  = fma2_(DX2, hh, s4[6]);  s4[7]  = fma2_(DX3, hh, s4[7]);
        hh = fma2_(DX2, h2, s3[2]);
        s4[8]  = fma2_(DX0, hh, s4[8]);  s4[9]  = fma2_(DX1, hh, s4[9]);
        s4[10] = fma2_(DX2, hh, s4[10]); s4[11] = fma2_(DX3, hh, s4[11]);
        hh = fma2_(DX3, h2, s3[3]);
        s4[12] = fma2_(DX0, hh, s4[12]); s4[13] = fma2_(DX1, hh, s4[13]);
        s4[14] = fma2_(DX2, hh, s4[14]); s4[15] = fma2_(DX3, hh, s4[15]);

        ull c1b = fma2_(THIRD, du, s1u);
        ull m3v = fma2_(mul2_(HALF, dv), c1b, s2);
        s3[0] = fma2_(DX0, m3v, s3[0]); s3[1] = fma2_(DX1, m3v, s3[1]);
        s3[2] = fma2_(DX2, m3v, s3[2]); s3[3] = fma2_(DX3, m3v, s3[3]);
        s2 = fma2_(dv, fma2_(HALF, du, s1u), s2);
        s1u = add2_(s1u, du);
    }

    // ---- S1 telescopes (same for all paths/lanes) ----
    float s1c0 = xsh[93] - xsh[0];
    float s1c1 = xsh[94] - xsh[1];
    float s1c2 = xsh[95] - xsh[2];
    float s1c3 = xsh[127] - xsh[96];
    float n1 = s1c0*s1c0 + s1c1*s1c1 + s1c2*s1c2 + s1c3*s1c3;

    ull n2p = mul2_(s2, s2);
    ull n3p = mul2_(s3[0], s3[0]);
    #pragma unroll
    for (int j = 1; j < 4; j++) n3p = fma2_(s3[j], s3[j], n3p);
    ull n4p = mul2_(s4[0], s4[0]);
    #pragma unroll
    for (int j = 1; j < 16; j++) n4p = fma2_(s4[j], s4[j], n4p);
    #pragma unroll
    for (int off = 8; off >= 1; off >>= 1) {
        n2p = add2_(n2p, __shfl_xor_sync(0xffffffffu, n2p, off));
        n3p = add2_(n3p, __shfl_xor_sync(0xffffffffu, n3p, off));
        n4p = add2_(n4p, __shfl_xor_sync(0xffffffffu, n4p, off));
    }
    float n2a, n2b, n3a, n3b, n4a, n4b;
    upk2(n2p, n2a, n2b); upk2(n3p, n3a, n3b); upk2(n4p, n4a, n4b);

    float lamA, l2A, l3A, l4A, lamB, l2B, l3B, l4B;
    solve_lam(n1, n2a, n3a, n4a, lamA, l2A, l3A, l4A);
    solve_lam(n1, n2b, n3b, n4b, lamB, l2B, l3B, l4B);

    // ---- accumulate normalized expected signature ----
    if (pre == 0) {
        float ls = lamA + lamB;
        atomicAdd(&sacc[0], ls * s1c0);
        atomicAdd(&sacc[1], ls * s1c1);
        atomicAdd(&sacc[2], ls * s1c2);
        atomicAdd(&sacc[3], ls * s1c3);
    }
    {
        float a, bb; upk2(s2, a, bb);
        atomicAdd(&sacc[4 + pre], l2A * a + l2B * bb);
    }
    #pragma unroll
    for (int j = 0; j < 4; j++) {
        float a, bb; upk2(s3[j], a, bb);
        atomicAdd(&sacc[20 + pre * 4 + j], l3A * a + l3B * bb);
    }
    #pragma unroll
    for (int j = 0; j < 16; j++) {
        float a, bb; upk2(s4[j], a, bb);
        atomicAdd(&sacc[84 + pre * 16 + j], l4A * a + l4B * bb);
    }
    __syncthreads();

    // ---- logit contraction: class c dot over SIGDIM, 8 warps ----
    int warp = tid >> 5, lane = tid & 31;
    for (int c = warp; c < NCLS; c += 8) {
        float sum = 0.f;
        #pragma unroll
        for (int i = 0; i < 10; i++) {          // 10 full 32-wide strips
            int j = lane + i * 32;
            sum = fmaf(sacc[j], __ldg(&Wf[c * SIGDIM + j]), sum);
        }
        {                                       // tail: 320..339
            int j = lane + 320;
            if (j < SIGDIM)
                sum = fmaf(sacc[j], __ldg(&Wf[c * SIGDIM + j]), sum);
        }
        #pragma unroll
        for (int off = 16; off; off >>= 1)
            sum += __shfl_xor_sync(0xffffffffu, sum, off);
        if (lane == 0)
            atomicAdd(&g_logits[b * NCLS + c], sum);
    }
}

// =====================================================================
// Kernel 4: scale + bias + log_softmax on 256x10 logits.
// =====================================================================
__global__ __launch_bounds__(256) void final_kernel(
    const float* __restrict__ bf, float* __restrict__ out)
{
    int warp = threadIdx.x >> 5, lane = threadIdx.x & 31;
    int b = blockIdx.x * 8 + warp;

    float logit = -3.402823466e38f;
    if (lane < NCLS)
        logit = __ldcg(&g_logits[b * NCLS + lane]) * (1.0f / (float)KPATHS) + bf[lane];

    float mx = logit;
    #pragma unroll
    for (int off = 16; off; off >>= 1)
        mx = fmaxf(mx, __shfl_xor_sync(0xffffffffu, mx, off));
    float e = (lane < NCLS) ? expf(logit - mx) : 0.f;
    float ssum = e;
    #pragma unroll
    for (int off = 16; off; off >>= 1)
        ssum += __shfl_xor_sync(0xffffffffu, ssum, off);
    if (lane < NCLS)
        out[b * NCLS + lane] = logit - mx - logf(ssum);
}

// =====================================================================
extern "C" void kernel_launch(void* const* d_in, const int* in_sizes, int n_in,
                              void* d_out, int out_size)
{
    const float* x      = (const float*)d_in[0];
    const float* W_mean = (const float*)d_in[1];
    const float* b_mean = (const float*)d_in[2];
    const float* W_cov  = (const float*)d_in[3];
    const float* b_cov  = (const float*)d_in[4];
    const float* W_fin  = (const float*)d_in[5];
    const float* b_fin  = (const float*)d_in[6];
    const float* eps    = (const float*)d_in[7];
    const int*   x_idx  = (const int*)  d_in[8];
    const int*   y_idx  = (const int*)  d_in[9];
    float* out = (float*)d_out;

    // 1) fused linears, champion 64x128 config (also zeroes g_logits)
    gemm_kernel<<<dim3(25, BATCH / 64), 256>>>(x, W_cov, b_cov, W_mean, b_mean);
    // 2) banded batched matmul -> newV
    newv_kernel<<<BATCH, 256>>>(eps, x_idx, y_idx);
    // 3) packed-delta f32x2 signatures + normalization + logits
    sig_kernel<<<BATCH * 2, 256>>>(x, W_fin);
    // 4) bias + log_softmax
    final_kernel<<<BATCH / 8, 256>>>(b_fin, out);
}

// round 16
// speedup vs baseline: 1.2939x; 1.0614x over previous
#include <cuda_runtime.h>

// Problem constants
#define BATCH   256
#define INDIM   159     // L1*(DIM+1) + L2
#define MDIM    93      // L2*DIM
#define MATEL   2976
#define KPATHS  64
#define NCLS    10
#define SIGDIM  340     // 4+16+64+256
#define KD      159
#define KC      40      // gemm k-chunk

typedef unsigned long long ull;

// ---------------- scratch (no allocations allowed) ----------------
__device__ __align__(16) float g_mean[BATCH * MDIM];
__device__ __align__(16) float g_cov [BATCH * MATEL];
__device__ __align__(16) float g_newV[BATCH * MDIM * KPATHS];   // [b][r][k]
__device__ __align__(16) float g_logits[BATCH * NCLS];          // atomic accumulators
__device__ unsigned int g_ticket;                               // last-block election

// ---------------- f32x2 packed helpers (sm_103a FFMA2 path) ----------------
__device__ __forceinline__ ull pk2(float lo, float hi) {
    ull r; asm("mov.b64 %0, {%1,%2};" : "=l"(r) : "f"(lo), "f"(hi)); return r;
}
__device__ __forceinline__ void upk2(ull v, float& lo, float& hi) {
    asm("mov.b64 {%0,%1}, %2;" : "=f"(lo), "=f"(hi) : "l"(v));
}
__device__ __forceinline__ ull fma2_(ull a, ull b, ull c) {
    ull d; asm("fma.rn.f32x2 %0, %1, %2, %3;" : "=l"(d) : "l"(a), "l"(b), "l"(c)); return d;
}
__device__ __forceinline__ ull mul2_(ull a, ull b) {
    ull d; asm("mul.rn.f32x2 %0, %1, %2;" : "=l"(d) : "l"(a), "l"(b)); return d;
}
__device__ __forceinline__ ull add2_(ull a, ull b) {
    ull d; asm("add.rn.f32x2 %0, %1, %2;" : "=l"(d) : "l"(a), "l"(b)); return d;
}

// =====================================================================
// Kernel 1 (fused): mean = x@W_mean^T + b_mean AND cov = x@W_cov^T + b_cov
// CHAMPION CONFIG: 64 batch x 128 n block tile; 8x4 register tile.
// is_mean blocks also zero g_logits + g_ticket (stream-ordered pre-sig).
// =====================================================================
__global__ __launch_bounds__(256) void gemm_kernel(
    const float* __restrict__ X,
    const float* __restrict__ Wc, const float* __restrict__ bc,
    const float* __restrict__ Wm, const float* __restrict__ bm)
{
    __shared__ float Ash[64][KC + 1];   // 10.5 KB
    __shared__ float Wsh[KC][132];      // 20.6 KB

    bool is_mean = (blockIdx.x == 24);
    const float* W    = is_mean ? Wm : Wc;
    const float* bias = is_mean ? bm : bc;
    float*       out  = is_mean ? g_mean : g_cov;
    int N  = is_mean ? MDIM : MATEL;
    int n0 = is_mean ? 0 : blockIdx.x * 128;
    int b0 = blockIdx.y * 64;
    int tid = threadIdx.x;

    if (is_mean) {
        for (int i = tid; i < BATCH * NCLS; i += 256) g_logits[i] = 0.f;
        if (tid == 0) g_ticket = 0u;
    }

    float acc[8][4] = {};
    int tn = tid & 31;                  // 4 consecutive n
    int tb = tid >> 5;                  // 8 consecutive batch rows

    for (int k0 = 0; k0 < KD; k0 += KC) {
        __syncthreads();
        for (int idx = tid; idx < 64 * KC; idx += 256) {
            int r = idx / KC, k = idx % KC;
            int gk = k0 + k;
            Ash[r][k] = (gk < KD) ? X[(b0 + r) * KD + gk] : 0.f;
        }
        for (int idx = tid; idx < KC * 128; idx += 256) {
            int n = idx / KC, k = idx % KC;
            int gk = k0 + k, gn = n0 + n;
            Wsh[k][n] = (gk < KD && gn < N) ? W[(size_t)gn * KD + gk] : 0.f;
        }
        __syncthreads();
        #pragma unroll 8
        for (int k = 0; k < KC; k++) {
            float4 w = *(const float4*)&Wsh[k][tn * 4];
            #pragma unroll
            for (int j = 0; j < 8; j++) {
                float a = Ash[tb * 8 + j][k];
                acc[j][0] = fmaf(a, w.x, acc[j][0]);
                acc[j][1] = fmaf(a, w.y, acc[j][1]);
                acc[j][2] = fmaf(a, w.z, acc[j][2]);
                acc[j][3] = fmaf(a, w.w, acc[j][3]);
            }
        }
    }
    #pragma unroll
    for (int j = 0; j < 8; j++)
        #pragma unroll
        for (int i = 0; i < 4; i++) {
            int n = n0 + tn * 4 + i;
            if (n < N)
                out[(size_t)(b0 + tb * 8 + j) * N + n] = acc[j][i] + bias[n];
        }
}

// =====================================================================
// Kernel 2: scatter sqrtCov -> banded M (93x93), newV = M@eps + mean.
// 3-row register blocking; balanced band pairing (tg with 30-tg).
// =====================================================================
__global__ __launch_bounds__(256) void newv_kernel(
    const float* __restrict__ eps, const int* __restrict__ xI,
    const int* __restrict__ yI)
{
    __shared__ float Msh[MDIM * MDIM];
    int b   = blockIdx.x;
    int tid = threadIdx.x;

    for (int i = tid; i < MDIM * MDIM; i += 256) Msh[i] = 0.f;
    __syncthreads();
    const float* covB = g_cov + (size_t)b * MATEL;
    for (int e = tid; e < MATEL; e += 256)
        Msh[xI[e] * MDIM + yI[e]] = covB[e];
    __syncthreads();

    int k4 = tid & 15;
    int tg = tid >> 4;
    const float* epsB = eps    + (size_t)b * MDIM * KPATHS + k4 * 4;
    float*       outB = g_newV + (size_t)b * MDIM * KPATHS + k4 * 4;

    #pragma unroll
    for (int pass = 0; pass < 2; pass++) {
        if (pass == 1 && tg == 15) break;
        int g    = pass ? 30 - tg : tg;
        int r0   = 3 * g;
        int cmax = 3 * g + 3;
        float a0x=0,a0y=0,a0z=0,a0w=0, a1x=0,a1y=0,a1z=0,a1w=0, a2x=0,a2y=0,a2z=0,a2w=0;
        const float* M0 = &Msh[r0 * MDIM];
        for (int c = 0; c < cmax; c++) {
            float4 ev = *(const float4*)(epsB + (size_t)c * KPATHS);
            float m0 = M0[c], m1 = M0[MDIM + c], m2 = M0[2 * MDIM + c];
            a0x = fmaf(m0, ev.x, a0x); a0y = fmaf(m0, ev.y, a0y);
            a0z = fmaf(m0, ev.z, a0z); a0w = fmaf(m0, ev.w, a0w);
            a1x = fmaf(m1, ev.x, a1x); a1y = fmaf(m1, ev.y, a1y);
            a1z = fmaf(m1, ev.z, a1z); a1w = fmaf(m1, ev.w, a1w);
            a2x = fmaf(m2, ev.x, a2x); a2y = fmaf(m2, ev.y, a2y);
            a2z = fmaf(m2, ev.z, a2z); a2w = fmaf(m2, ev.w, a2w);
        }
        float mn0 = g_mean[b * MDIM + r0];
        float mn1 = g_mean[b * MDIM + r0 + 1];
        float mn2 = g_mean[b * MDIM + r0 + 2];
        *(float4*)(outB + (size_t)(r0    ) * KPATHS) = make_float4(a0x+mn0, a0y+mn0, a0z+mn0, a0w+mn0);
        *(float4*)(outB + (size_t)(r0 + 1) * KPATHS) = make_float4(a1x+mn1, a1y+mn1, a1z+mn1, a1w+mn1);
        *(float4*)(outB + (size_t)(r0 + 2) * KPATHS) = make_float4(a2x+mn2, a2y+mn2, a2z+mn2, a2w+mn2);
    }
}

// =====================================================================
// Kernel 3: signature via f32x2 packed Chen steps, TWO PATHS PER LANE,
// precomputed packed deltas in shared. NOW: 128 thr = 8 path-pairs =
// 16 paths (one k-quarter); grid = BATCH*4 = 1024; ~24 KB smem ->
// __launch_bounds__(128,7): 7 blocks/SM = 43.75% occ, single wave.
// Epilogue: norms, Newton lambda, expected-sig, logit contraction ->
// global atomics; LAST block (ticket) runs per-thread softmax for all
// 256 rows and writes the output (no separate final kernel).
// =====================================================================
__device__ __forceinline__ void solve_lam(float n1, float n2, float n3, float n4,
                                          float& lam, float& lam2v,
                                          float& lam3, float& lam4)
{
    float norm2 = 1.0f + (((n1 + n2) + n3) + n4);
    float xc  = fmaxf(norm2, 4.0f);
    float psi = (norm2 <= 4.0f) ? norm2 : (4.0f + 16.0f * (0.25f - 1.0f / xc));
    float q = psi - 1.0f;
    float t = 1.0f;
    t = fminf(t, q / n1);
    t = fminf(t, sqrtf(q / n2));
    t = fminf(t, exp2f((1.0f / 3.0f) * log2f(q / n3)));
    t = fminf(t, sqrtf(sqrtf(q / n4)));
    float cN = -q;
    #pragma unroll
    for (int it = 0; it < 12; it++) {
        float f  = fmaf(fmaf(fmaf(fmaf(n4, t, n3), t, n2), t, n1), t, cN);
        float fp = fmaf(fmaf(fmaf(4.0f * n4, t, 3.0f * n3), t, 2.0f * n2), t, n1);
        fp = fmaxf(fp, 1e-30f);
        t  = fmaxf(t - f / fp, 0.0f);
    }
    lam2v = t;
    lam   = sqrtf(t);
    lam3  = lam2v * lam;
    lam4  = lam2v * lam2v;
}

__global__ __launch_bounds__(128, 7) void sig_kernel(
    const float* __restrict__ x,  const float* __restrict__ Wf,
    const float* __restrict__ bf, float* __restrict__ out)
{
    __shared__ float  xsh[INDIM + 1];           // 0.64 KB
    __shared__ float  nvsh[MDIM * 16];          // newV quarter: [r][k] 5.95 KB
    __shared__ float4 dxsh[62 * 8 * 2];         // packed deltas 15.9 KB
    __shared__ float  sacc[SIGDIM];             // 1.36 KB
    __shared__ unsigned int s_last;

    int b    = blockIdx.x >> 2;
    int kq   = blockIdx.x & 3;                  // k quarter (16 paths)
    int tid  = threadIdx.x;
    const float* xb = x + (size_t)b * INDIM;

    for (int i = tid; i < INDIM; i += 128) xsh[i] = xb[i];
    const float* nvb = g_newV + (size_t)b * MDIM * KPATHS + kq * 16;
    for (int i = tid; i < MDIM * 16; i += 128)
        nvsh[i] = nvb[(size_t)(i >> 4) * KPATHS + (i & 15)];
    for (int i = tid; i < SIGDIM; i += 128) sacc[i] = 0.f;
    __syncthreads();

    // ---- precompute packed deltas: step s, path-pair pp (0..7) ----
    for (int i = tid; i < 62 * 8; i += 128) {
        int s = i >> 3, pp = i & 7;
        int m = s >> 1;
        int r = 3 * m;
        int kA = 2 * pp, kB = kA + 1;
        float n0A = nvsh[r * 16 + kA],       n0B = nvsh[r * 16 + kB];
        float n1A = nvsh[(r + 1) * 16 + kA], n1B = nvsh[(r + 1) * 16 + kB];
        float n2A = nvsh[(r + 2) * 16 + kA], n2B = nvsh[(r + 2) * 16 + kB];
        float d0A, d0B, d1A, d1B, d2A, d2B, dt;
        if ((s & 1) == 0) {     // new_m - known_m
            d0A = n0A - xsh[r];     d0B = n0B - xsh[r];
            d1A = n1A - xsh[r + 1]; d1B = n1B - xsh[r + 1];
            d2A = n2A - xsh[r + 2]; d2B = n2B - xsh[r + 2];
            dt  = xsh[128 + m] - xsh[96 + m];
        } else {                // known_{m+1} - new_m
            d0A = xsh[r + 3] - n0A; d0B = xsh[r + 3] - n0B;
            d1A = xsh[r + 4] - n1A; d1B = xsh[r + 4] - n1B;
            d2A = xsh[r + 5] - n2A; d2B = xsh[r + 5] - n2B;
            dt  = xsh[97 + m] - xsh[128 + m];
        }
        float4* d = &dxsh[(s * 8 + pp) * 2];
        d[0] = make_float4(d0A, d0B, d1A, d1B);
        d[1] = make_float4(d2A, d2B, dt, dt);
    }
    __syncthreads();

    // ---- packed signature main loop: 2 paths per lane ----
    int pp  = tid >> 4;                 // 0..7
    int pre = tid & 15;
    int i1 = pre >> 2, i2 = pre & 3;
    const char* dbase  = (const char*)&dxsh[pp * 2];
    const char* dubase = dbase + i1 * 8;
    const char* dvbase = dbase + i2 * 8;

    const ull QUARTER = 0x3E8000003E800000ULL;   // (0.25, 0.25)
    const ull HALF    = 0x3F0000003F000000ULL;   // (0.5, 0.5)
    const ull THIRD   = pk2(1.0f / 3.0f, 1.0f / 3.0f);

    ull s1u = 0, s2 = 0;
    ull s3[4] = {0, 0, 0, 0};
    ull s4[16] = {0,0,0,0,0,0,0,0,0,0,0,0,0,0,0,0};

    for (int s = 0; s < 62; s++) {
        float4 f0 = ((const float4*)(dbase + s * 256))[0];
        float4 f1 = ((const float4*)(dbase + s * 256))[1];
        ull DX0 = ((ull*)&f0)[0], DX1 = ((ull*)&f0)[1];
        ull DX2 = ((ull*)&f1)[0], DX3 = ((ull*)&f1)[1];
        ull du = *(const ull*)(dubase + s * 256);
        ull dv = *(const ull*)(dvbase + s * 256);

        ull cc1 = fma2_(QUARTER, du, s1u);
        ull cc2 = fma2_(mul2_(THIRD, dv), cc1, s2);
        ull h2  = mul2_(HALF, cc2);
        ull hh;
        hh = fma2_(DX0, h2, s3[0]);
        s4[0]  = fma2_(DX0, hh, s4[0]);  s4[1]  = fma2_(DX1, hh, s4[1]);
        s4[2]  = fma2_(DX2, hh, s4[2]);  s4[3]  = fma2_(DX3, hh, s4[3]);
        hh = fma2_(DX1, h2, s3[1]);
        s4[4]  = fma2_(DX0, hh, s4[4]);  s4[5]  = fma2_(DX1, hh, s4[5]);
        s4[6]  = fma2_(DX2, hh, s4[6]);  s4[7]  = fma2_(DX3, hh, s4[7]);
        hh = fma2_(DX2, h2, s3[2]);
        s4[8]  = fma2_(DX0, hh, s4[8]);  s4[9]  = fma2_(DX1, hh, s4[9]);
        s4[10] = fma2_(DX2, hh, s4[10]); s4[11] = fma2_(DX3, hh, s4[11]);
        hh = fma2_(DX3, h2, s3[3]);
        s4[12] = fma2_(DX0, hh, s4[12]); s4[13] = fma2_(DX1, hh, s4[13]);
        s4[14] = fma2_(DX2, hh, s4[14]); s4[15] = fma2_(DX3, hh, s4[15]);

        ull c1b = fma2_(THIRD, du, s1u);
        ull m3v = fma2_(mul2_(HALF, dv), c1b, s2);
        s3[0] = fma2_(DX0, m3v, s3[0]); s3[1] = fma2_(DX1, m3v, s3[1]);
        s3[2] = fma2_(DX2, m3v, s3[2]); s3[3] = fma2_(DX3, m3v, s3[3]);
        s2 = fma2_(dv, fma2_(HALF, du, s1u), s2);
        s1u = add2_(s1u, du);
    }

    // ---- S1 telescopes (same for all paths/lanes) ----
    float s1c0 = xsh[93] - xsh[0];
    float s1c1 = xsh[94] - xsh[1];
    float s1c2 = xsh[95] - xsh[2];
    float s1c3 = xsh[127] - xsh[96];
    float n1 = s1c0*s1c0 + s1c1*s1c1 + s1c2*s1c2 + s1c3*s1c3;

    ull n2p = mul2_(s2, s2);
    ull n3p = mul2_(s3[0], s3[0]);
    #pragma unroll
    for (int j = 1; j < 4; j++) n3p = fma2_(s3[j], s3[j], n3p);
    ull n4p = mul2_(s4[0], s4[0]);
    #pragma unroll
    for (int j = 1; j < 16; j++) n4p = fma2_(s4[j], s4[j], n4p);
    #pragma unroll
    for (int off = 8; off >= 1; off >>= 1) {
        n2p = add2_(n2p, __shfl_xor_sync(0xffffffffu, n2p, off));
        n3p = add2_(n3p, __shfl_xor_sync(0xffffffffu, n3p, off));
        n4p = add2_(n4p, __shfl_xor_sync(0xffffffffu, n4p, off));
    }
    float n2a, n2b, n3a, n3b, n4a, n4b;
    upk2(n2p, n2a, n2b); upk2(n3p, n3a, n3b); upk2(n4p, n4a, n4b);

    float lamA, l2A, l3A, l4A, lamB, l2B, l3B, l4B;
    solve_lam(n1, n2a, n3a, n4a, lamA, l2A, l3A, l4A);
    solve_lam(n1, n2b, n3b, n4b, lamB, l2B, l3B, l4B);

    // ---- accumulate normalized expected signature ----
    if (pre == 0) {
        float ls = lamA + lamB;
        atomicAdd(&sacc[0], ls * s1c0);
        atomicAdd(&sacc[1], ls * s1c1);
        atomicAdd(&sacc[2], ls * s1c2);
        atomicAdd(&sacc[3], ls * s1c3);
    }
    {
        float a, bb; upk2(s2, a, bb);
        atomicAdd(&sacc[4 + pre], l2A * a + l2B * bb);
    }
    #pragma unroll
    for (int j = 0; j < 4; j++) {
        float a, bb; upk2(s3[j], a, bb);
        atomicAdd(&sacc[20 + pre * 4 + j], l3A * a + l3B * bb);
    }
    #pragma unroll
    for (int j = 0; j < 16; j++) {
        float a, bb; upk2(s4[j], a, bb);
        atomicAdd(&sacc[84 + pre * 16 + j], l4A * a + l4B * bb);
    }
    __syncthreads();

    // ---- logit contraction: class c dot over SIGDIM, 4 warps ----
    int warp = tid >> 5, lane = tid & 31;
    for (int c = warp; c < NCLS; c += 4) {
        float sum = 0.f;
        #pragma unroll
        for (int i = 0; i < 10; i++) {          // 10 full 32-wide strips
            int j = lane + i * 32;
            sum = fmaf(sacc[j], __ldg(&Wf[c * SIGDIM + j]), sum);
        }
        {                                       // tail: 320..339
            int j = lane + 320;
            if (j < SIGDIM)
                sum = fmaf(sacc[j], __ldg(&Wf[c * SIGDIM + j]), sum);
        }
        #pragma unroll
        for (int off = 16; off; off >>= 1)
            sum += __shfl_xor_sync(0xffffffffu, sum, off);
        if (lane == 0) {
            atomicAdd(&g_logits[b * NCLS + c], sum);
            __threadfence();        // order this thread's logit add before ticket
        }
    }
    __syncthreads();

    // ---- last-block election: winner does per-thread softmax ----
    if (tid == 0) {
        __threadfence();
        s_last = (atomicAdd(&g_ticket, 1u) == 4u * BATCH - 1u) ? 1u : 0u;
    }
    __syncthreads();
    if (s_last) {
        for (int r = tid; r < BATCH; r += 128) {
            float lg[NCLS];
            float mx = -3.402823466e38f;
            #pragma unroll
            for (int c = 0; c < NCLS; c++) {
                lg[c] = __ldcg(&g_logits[r * NCLS + c]) * (1.0f / (float)KPATHS)
                        + __ldg(&bf[c]);
                mx = fmaxf(mx, lg[c]);
            }
            float ssum = 0.f;
            #pragma unroll
            for (int c = 0; c < NCLS; c++) ssum += expf(lg[c] - mx);
            float lse = logf(ssum);
            #pragma unroll
            for (int c = 0; c < NCLS; c++)
                out[r * NCLS + c] = lg[c] - mx - lse;
        }
    }
}

// =====================================================================
extern "C" void kernel_launch(void* const* d_in, const int* in_sizes, int n_in,
                              void* d_out, int out_size)
{
    const float* x      = (const float*)d_in[0];
    const float* W_mean = (const float*)d_in[1];
    const float* b_mean = (const float*)d_in[2];
    const float* W_cov  = (const float*)d_in[3];
    const float* b_cov  = (const float*)d_in[4];
    const float* W_fin  = (const float*)d_in[5];
    const float* b_fin  = (const float*)d_in[6];
    const float* eps    = (const float*)d_in[7];
    const int*   x_idx  = (const int*)  d_in[8];
    const int*   y_idx  = (const int*)  d_in[9];
    float* out = (float*)d_out;

    // 1) fused linears, champion 64x128 config (zeroes g_logits + g_ticket)
    gemm_kernel<<<dim3(25, BATCH / 64), 256>>>(x, W_cov, b_cov, W_mean, b_mean);
    // 2) banded batched matmul -> newV
    newv_kernel<<<BATCH, 256>>>(eps, x_idx, y_idx);
    // 3) packed-delta f32x2 signatures (128thr/7blk) + logits + softmax
    sig_kernel<<<BATCH * 4, 128>>>(x, W_fin, b_fin, out);
}